// round 12
// baseline (speedup 1.0000x reference)
#include <cuda_runtime.h>
#include <cstdint>
#include <math.h>

#define BB     16
#define HH     1024
#define TCNT   1500
#define MAXTOK 192
#define TS     30        // time positions per K1/K3 block (divides 1500)
#define XCOLS  32        // TS + 2 halo
#define XSTR   33        // padded smem row stride (conflict-free)
#define NTILE  50        // 1500 / TS
#define INV2T2 4.0816326530612246f   // 1/(2*0.35^2)

// ---------------- scratch (__device__ globals; no allocation) ----------------
static __device__ float g_raw[BB * TCNT];
static __device__ float g_sw[BB * TCNT];
static __device__ float g_cen[BB * TCNT];
static __device__ float g_assign[BB * TCNT * MAXTOK];   // 18.4 MB
static __device__ float g_colsum[BB * MAXTOK];
static __device__ float g_rnorm[BB * MAXTOK];
static __device__ float g_massdiff[BB];

// ---------------- packed f32x2 helpers (sm_100+ PTX) ----------------
__device__ __forceinline__ unsigned long long pk2(float a, float b) {
    unsigned long long r;
    asm("mov.b64 %0, {%1, %2};" : "=l"(r) : "f"(a), "f"(b));
    return r;
}
__device__ __forceinline__ unsigned long long fma2(unsigned long long a,
                                                   unsigned long long b,
                                                   unsigned long long c) {
    unsigned long long d;
    asm("fma.rn.f32x2 %0, %1, %2, %3;" : "=l"(d) : "l"(a), "l"(b), "l"(c));
    return d;
}
__device__ __forceinline__ unsigned long long add2(unsigned long long a,
                                                   unsigned long long b) {
    unsigned long long d;
    asm("add.rn.f32x2 %0, %1, %2;" : "=l"(d) : "l"(a), "l"(b));
    return d;
}
__device__ __forceinline__ void unpk2(unsigned long long v, float& lo, float& hi) {
    asm("mov.b64 {%0, %1}, %2;" : "=f"(lo), "=f"(hi) : "l"(v));
}

__device__ __forceinline__ int clip_tok(int t) {
    return t < 1 ? 1 : (t > MAXTOK ? MAXTOK : t);
}

// =====================================================================
// K1: fused conv1d(K=3, SAME) -> silu -> proj -> softplus -> mask  => raw[b,t]
// grid (NTILE, BB), 256 threads. Each warp owns 128 h_out as 64 pairs,
// lanes split h_in (coalesced W reads), packed f32x2 accumulators over TS.
// =====================================================================
__global__ void __launch_bounds__(256, 1)
k1_conv_raw(const float* __restrict__ enc, const float* __restrict__ cw,
            const float* __restrict__ cb, const float* __restrict__ pw,
            const float* __restrict__ pb, const int* __restrict__ elen)
{
    extern __shared__ float sh[];
    float* x_sm  = sh;                 // HH * XSTR
    float* s_raw = sh + HH * XSTR;     // TS

    const int b    = blockIdx.y;
    const int t0   = blockIdx.x * TS;
    const int tid  = threadIdx.x;
    const int lane = tid & 31;
    const int w    = tid >> 5;         // 8 warps

    if (tid < TS) s_raw[tid] = 0.f;

    const float* encb = enc + (size_t)b * HH * TCNT;
    for (int idx = tid; idx < HH * XCOLS; idx += 256) {
        int hin = idx >> 5, c = idx & 31;
        int t = t0 - 1 + c;
        float v = 0.f;
        if (t >= 0 && t < TCNT) v = encb[(size_t)hin * TCNT + t];
        x_sm[hin * XSTR + c] = v;
    }
    __syncthreads();

    float runsum = 0.f;
    #pragma unroll 1
    for (int p = 0; p < 64; ++p) {
        const int hoA = (w << 7) + (p << 1);
        const float* wAr = cw + (size_t)hoA * (HH * 3);
        const float* wBr = wAr + HH * 3;

        unsigned long long acc2[TS];
        #pragma unroll
        for (int j = 0; j < TS; ++j) acc2[j] = 0ull;

        // prefetch first weight triplets
        float a0 = wAr[lane * 3 + 0], a1 = wAr[lane * 3 + 1], a2 = wAr[lane * 3 + 2];
        float b0 = wBr[lane * 3 + 0], b1 = wBr[lane * 3 + 1], b2 = wBr[lane * 3 + 2];

        #pragma unroll 2
        for (int i = 0; i < 32; ++i) {
            unsigned long long w20 = pk2(a0, b0), w21 = pk2(a1, b1), w22 = pk2(a2, b2);
            const int hin = (i << 5) + lane;
            const float* xr = x_sm + hin * XSTR;
            if (i < 31) {   // prefetch next iteration's weights (hide L2 latency)
                int nh = ((i + 1) << 5) + lane;
                a0 = wAr[nh * 3 + 0]; a1 = wAr[nh * 3 + 1]; a2 = wAr[nh * 3 + 2];
                b0 = wBr[nh * 3 + 0]; b1 = wBr[nh * 3 + 1]; b2 = wBr[nh * 3 + 2];
            }
            #pragma unroll
            for (int c = 0; c < XCOLS; ++c) {
                float xv = xr[c];
                unsigned long long x2 = pk2(xv, xv);
                if (c < TS)            acc2[c]     = fma2(x2, w20, acc2[c]);
                if (c >= 1 && c <= TS) acc2[c - 1] = fma2(x2, w21, acc2[c - 1]);
                if (c >= 2)            acc2[c - 2] = fma2(x2, w22, acc2[c - 2]);
            }
        }

        // cross-lane reduction; lane j keeps the (hoA, hoB) sums for t = t0+j
        float mA = 0.f, mB = 0.f;
        #pragma unroll
        for (int j = 0; j < TS; ++j) {
            unsigned long long v = acc2[j];
            #pragma unroll
            for (int off = 16; off > 0; off >>= 1)
                v = add2(v, __shfl_xor_sync(0xffffffffu, v, off));
            if (lane == j) unpk2(v, mA, mB);
        }
        if (lane < TS) {
            float vA = mA + cb[hoA];
            float vB = mB + cb[hoA + 1];
            float sA = __fdividef(vA, 1.f + __expf(-vA));   // silu
            float sB = __fdividef(vB, 1.f + __expf(-vB));
            runsum += sA * pw[hoA] + sB * pw[hoA + 1];
        }
    }
    if (lane < TS) atomicAdd(&s_raw[lane], runsum);
    __syncthreads();

    if (tid < TS) {
        int t = t0 + tid;
        float x = s_raw[tid] + pb[0];
        float sp = (x > 20.f) ? x : log1pf(expf(x));   // stable softplus
        float r = sp + 1e-4f;
        if (t >= elen[b]) r = 0.f;                     // time mask
        g_raw[b * TCNT + t] = r;
    }
}

// =====================================================================
// K2: per-batch mass, scale, |mass-tok|, cumsum -> centers, sw.
// Also zeroes g_colsum. grid(BB), 512 threads.
// =====================================================================
__global__ void k2_scan(const int* __restrict__ ttl)
{
    const int b = blockIdx.x;
    const int tid = threadIdx.x;   // 512
    __shared__ float sm[16];
    __shared__ float wsum[16];
    __shared__ float sh_scale, sh_carry;

    if (tid < MAXTOK) g_colsum[b * MAXTOK + tid] = 0.f;

    float local = 0.f;
    for (int t = tid; t < TCNT; t += 512) local += g_raw[b * TCNT + t];
    #pragma unroll
    for (int off = 16; off > 0; off >>= 1)
        local += __shfl_xor_sync(0xffffffffu, local, off);
    if ((tid & 31) == 0) sm[tid >> 5] = local;
    __syncthreads();
    if (tid < 16) {
        float v = sm[tid];
        #pragma unroll
        for (int off = 8; off > 0; off >>= 1)
            v += __shfl_xor_sync(0x0000ffffu, v, off);
        if (tid == 0) {
            int tok = clip_tok(ttl[b]);
            g_massdiff[b] = fabsf(v - (float)tok);
            sh_scale = (float)tok / fmaxf(v, 1e-6f);
            sh_carry = 0.f;
        }
    }
    __syncthreads();
    const float scale = sh_scale;

    for (int tile = 0; tile < 3; ++tile) {
        int t = tile * 512 + tid;
        float v = (t < TCNT) ? g_raw[b * TCNT + t] * scale : 0.f;
        float x = v;
        #pragma unroll
        for (int off = 1; off < 32; off <<= 1) {
            float y = __shfl_up_sync(0xffffffffu, x, off);
            if ((tid & 31) >= off) x += y;
        }
        if ((tid & 31) == 31) wsum[tid >> 5] = x;
        __syncthreads();
        if (tid < 16) {
            float y = wsum[tid];
            #pragma unroll
            for (int off = 1; off < 16; off <<= 1) {
                float z = __shfl_up_sync(0x0000ffffu, y, off);
                if (tid >= off) y += z;
            }
            wsum[tid] = y;   // inclusive warp-total scan
        }
        __syncthreads();
        float offset = (tid >= 32) ? wsum[(tid >> 5) - 1] : 0.f;
        float incl = sh_carry + offset + x;
        if (t < TCNT) {
            g_cen[b * TCNT + t] = incl - 0.5f * v;
            g_sw[b * TCNT + t]  = v;
        }
        __syncthreads();
        if (tid == 0) sh_carry += wsum[15];
        __syncthreads();
    }
}

// =====================================================================
// K3: assign[b,t,k] = exp(-(center-tc_k)^2/(2*tau^2)) * sw ; + colsums
// grid (NTILE, BB), 192 threads (one per token slot).
// =====================================================================
__global__ void k3_assign()
{
    const int b  = blockIdx.y;
    const int t0 = blockIdx.x * TS;
    const int k  = threadIdx.x;   // 192
    __shared__ float sc[TS], ss[TS];
    if (k < TS) {
        sc[k] = g_cen[b * TCNT + t0 + k];
        ss[k] = g_sw[b * TCNT + t0 + k];
    }
    __syncthreads();
    const float tc = (float)k + 0.5f;
    float acc = 0.f;
    float* ap = g_assign + ((size_t)b * TCNT + t0) * MAXTOK + k;
    #pragma unroll 6
    for (int i = 0; i < TS; ++i) {
        float d = sc[i] - tc;
        float a = __expf(-d * d * INV2T2) * ss[i];
        ap[(size_t)i * MAXTOK] = a;
        acc += a;
    }
    atomicAdd(&g_colsum[b * MAXTOK + k], acc);
}

// K3b: rnorm[b,k] = tok_mask / max(colsum, eps)
__global__ void k3b_rnorm(const int* __restrict__ ttl)
{
    int b = blockIdx.x, k = threadIdx.x;
    int tok = clip_tok(ttl[b]);
    float cs = g_colsum[b * MAXTOK + k];
    g_rnorm[b * MAXTOK + k] = (k < tok) ? 1.0f / fmaxf(cs, 1e-6f) : 0.f;
}

// =====================================================================
// K4: acoustic[b,k,h] = sum_t assign[b,t,k]*rnorm[b,k] * enc[b,h,t]
// smem-tiled GEMM: BM=64(h) x BN=64(k) x BK=16(t), 256 thr, 4x4 microtile.
// grid (16, 3, 16).
// =====================================================================
__global__ void __launch_bounds__(256)
k4_gemm(const float* __restrict__ enc, float* __restrict__ out)
{
    const int b  = blockIdx.z;
    const int k0 = blockIdx.y * 64;
    const int h0 = blockIdx.x * 64;
    __shared__ float es[16][65];
    __shared__ float as[16][64];
    __shared__ float rn[64];
    const int tid = threadIdx.x;
    const int tx = tid & 15, ty = tid >> 4;
    if (tid < 64) rn[tid] = g_rnorm[b * MAXTOK + k0 + tid];

    float c[4][4];
    #pragma unroll
    for (int j = 0; j < 4; ++j)
        #pragma unroll
        for (int i = 0; i < 4; ++i) c[j][i] = 0.f;

    const float* encb = enc + ((size_t)b * HH + h0) * TCNT;
    const float* ab   = g_assign + (size_t)b * TCNT * MAXTOK + k0;

    for (int t0 = 0; t0 < TCNT; t0 += 16) {
        #pragma unroll
        for (int l = tid; l < 1024; l += 256) {
            int hh = l >> 4, tt = l & 15; int t = t0 + tt;
            es[tt][hh] = (t < TCNT) ? encb[(size_t)hh * TCNT + t] : 0.f;
        }
        #pragma unroll
        for (int l = tid; l < 1024; l += 256) {
            int tt = l >> 6, kk = l & 63; int t = t0 + tt;
            as[tt][kk] = (t < TCNT) ? ab[(size_t)t * MAXTOK + kk] : 0.f;
        }
        __syncthreads();
        #pragma unroll
        for (int tt = 0; tt < 16; ++tt) {
            float av[4], bv[4];
            #pragma unroll
            for (int i = 0; i < 4; ++i) av[i] = es[tt][ty * 4 + i];
            #pragma unroll
            for (int j = 0; j < 4; ++j) bv[j] = as[tt][tx * 4 + j];
            #pragma unroll
            for (int j = 0; j < 4; ++j)
                #pragma unroll
                for (int i = 0; i < 4; ++i) c[j][i] += bv[j] * av[i];
        }
        __syncthreads();
    }
    #pragma unroll
    for (int j = 0; j < 4; ++j) {
        float rj = rn[tx * 4 + j];
        float4 v = make_float4(c[j][0] * rj, c[j][1] * rj, c[j][2] * rj, c[j][3] * rj);
        *(float4*)(out + (((size_t)b * MAXTOK) + (k0 + tx * 4 + j)) * HH + h0 + ty * 4) = v;
    }
}

// =====================================================================
// K5: write tok_len (as float) + alignment_loss into the tail of d_out,
// zero any remaining tail padding.
// =====================================================================
__global__ void k5_final(float* __restrict__ out, const int* __restrict__ ttl, int out_size)
{
    __shared__ float s_loss;
    int tid = threadIdx.x;
    float v = (tid < BB) ? g_massdiff[tid] : 0.f;
    #pragma unroll
    for (int off = 16; off > 0; off >>= 1)
        v += __shfl_xor_sync(0xffffffffu, v, off);
    if (tid == 0) s_loss = v * (0.25f / (float)BB);
    __syncthreads();
    const int base = BB * MAXTOK * HH;   // 3145728
    for (int i = base + tid; i < out_size; i += blockDim.x) {
        int r = i - base;
        float val = 0.f;
        if (r < BB)       val = (float)clip_tok(ttl[r]);
        else if (r == BB) val = s_loss;
        out[i] = val;
    }
}

// =====================================================================
extern "C" void kernel_launch(void* const* d_in, const int* in_sizes, int n_in,
                              void* d_out, int out_size)
{
    const float* enc  = (const float*)d_in[0];
    const int*   elen = (const int*)  d_in[1];
    const int*   ttl  = (const int*)  d_in[2];
    const float* cw   = (const float*)d_in[3];
    const float* cb   = (const float*)d_in[4];
    const float* pw   = (const float*)d_in[5];
    const float* pb   = (const float*)d_in[6];
    float* out = (float*)d_out;

    const int smem1 = (HH * XSTR + TS) * (int)sizeof(float);   // ~135 KB
    cudaFuncSetAttribute(k1_conv_raw, cudaFuncAttributeMaxDynamicSharedMemorySize, smem1);

    k1_conv_raw<<<dim3(NTILE, BB), 256, smem1>>>(enc, cw, cb, pw, pb, elen);
    k2_scan<<<BB, 512>>>(ttl);
    k3_assign<<<dim3(NTILE, BB), MAXTOK>>>();
    k3b_rnorm<<<BB, MAXTOK>>>(ttl);
    k4_gemm<<<dim3(16, 3, BB), 256>>>(enc, out);
    if (out_size > BB * MAXTOK * HH)
        k5_final<<<1, 64>>>(out, ttl, out_size);
}

// round 16
// speedup vs baseline: 2.5741x; 2.5741x over previous
#include <cuda_runtime.h>
#include <cuda_fp16.h>
#include <cstdint>
#include <math.h>

#define BB     16
#define HH     1024
#define TCNT   1500
#define MAXTOK 192
#define TS     30
#define NTILE  50
#define INV2T2 4.0816326530612246f

// ---- K1 HMMA GEMM config ----
#define NCH    48            // 3 shifts * 16 hin-chunks of 64
#define OFF_A1 0
#define OFF_A2 16384
#define OFF_B1 32768
#define OFF_B2 49152
#define STG    65536         // bytes per pipeline stage
#define OFF_CB 131072        // 128 floats
#define OFF_PW 131584        // 128 floats
#define SMEM_K1 132096
#define HSC_DOWN 0x14001400u // fp16x2 {2^-10, 2^-10}
#define WRES_UP  1024.f      // b2 stored * 2^10

// ---------------- scratch (__device__ globals; no allocation) ----------------
static __device__ float  g_raw[BB * TCNT];
static __device__ float  g_sw[BB * TCNT];
static __device__ float  g_cen[BB * TCNT];
static __device__ float  g_assign[BB * TCNT * MAXTOK];
static __device__ float  g_colsum[BB * MAXTOK];
static __device__ float  g_rnorm[BB * MAXTOK];
static __device__ float  g_massdiff[BB];
static __device__ float  g_partial[BB * TCNT];
static __device__ __align__(128) __half g_a1[(size_t)BB * TCNT * HH];  // x1 [b,t,h]
static __device__ __align__(128) __half g_a2[(size_t)BB * TCNT * HH];  // x-x1
static __device__ __align__(128) __half g_b1[(size_t)HH * 3 * HH];     // w1 [ho, s*1024+hin]
static __device__ __align__(128) __half g_b2[(size_t)HH * 3 * HH];     // (w-w1)*2^10 (normal)

__device__ __forceinline__ int clip_tok(int t) {
    return t < 1 ? 1 : (t > MAXTOK ? MAXTOK : t);
}

// ---------------- PTX helpers (base-target safe) ----------------
__device__ __forceinline__ uint32_t smem_u32(const void* p) {
    uint32_t a;
    asm("{ .reg .u64 t; cvta.to.shared.u64 t, %1; cvt.u32.u64 %0, t; }" : "=r"(a) : "l"(p));
    return a;
}
__device__ __forceinline__ void cpa16(uint32_t dst, const void* src, uint32_t nbytes) {
    asm volatile("cp.async.cg.shared.global [%0], [%1], 16, %2;"
                 :: "r"(dst), "l"(src), "r"(nbytes) : "memory");
}
__device__ __forceinline__ void cpa_commit() {
    asm volatile("cp.async.commit_group;" ::: "memory");
}
__device__ __forceinline__ void cpa_wait1() {
    asm volatile("cp.async.wait_group 1;" ::: "memory");
}
__device__ __forceinline__ void cpa_wait0() {
    asm volatile("cp.async.wait_group 0;" ::: "memory");
}
__device__ __forceinline__ void ldsm4(uint32_t* r, uint32_t a) {
    asm volatile("ldmatrix.sync.aligned.m8n8.x4.shared.b16 {%0,%1,%2,%3}, [%4];"
                 : "=r"(r[0]), "=r"(r[1]), "=r"(r[2]), "=r"(r[3]) : "r"(a));
}
__device__ __forceinline__ uint32_t hmul2(uint32_t a, uint32_t b) {
    uint32_t d;
    asm("mul.rn.f16x2 %0, %1, %2;" : "=r"(d) : "r"(a), "r"(b));
    return d;
}
__device__ __forceinline__ void mma16816(float* c, const uint32_t* a, uint32_t b0, uint32_t b1) {
    asm volatile(
        "mma.sync.aligned.m16n8k16.row.col.f32.f16.f16.f32 "
        "{%0,%1,%2,%3}, {%4,%5,%6,%7}, {%8,%9}, {%0,%1,%2,%3};"
        : "+f"(c[0]), "+f"(c[1]), "+f"(c[2]), "+f"(c[3])
        : "r"(a[0]), "r"(a[1]), "r"(a[2]), "r"(a[3]), "r"(b0), "r"(b1));
}

// =====================================================================
// P1: transpose + fp16-split enc [b,h,t] -> g_a1/g_a2 [b,t,h]
// grid (47, 32, 16), block (32, 8)
// =====================================================================
__global__ void p_enc(const float* __restrict__ enc)
{
    __shared__ float tile[32][33];
    const int b = blockIdx.z, h0 = blockIdx.y * 32, t0 = blockIdx.x * 32;
    const int tx = threadIdx.x, ty = threadIdx.y;
    #pragma unroll
    for (int j = 0; j < 4; ++j) {
        int h = h0 + ty + 8 * j, t = t0 + tx;
        tile[ty + 8 * j][tx] = (t < TCNT) ? enc[((size_t)b * HH + h) * TCNT + t] : 0.f;
    }
    __syncthreads();
    #pragma unroll
    for (int j = 0; j < 4; ++j) {
        int t = t0 + ty + 8 * j, h = h0 + tx;
        if (t < TCNT) {
            float v = tile[tx][ty + 8 * j];
            __half a = __float2half(v);
            __half r = __float2half(v - __half2float(a));
            size_t o = ((size_t)b * TCNT + t) * HH + h;
            g_a1[o] = a; g_a2[o] = r;
        }
    }
}

// P2: expand + split weights: g_b1 = fp16(w); g_b2 = (w - fp16(w)) * 2^10
// (rebalanced into fp16 normal range; consumer multiplies A1 by 2^-10).
// Also zeroes g_partial. grid(1024), block(1024)
__global__ void p_w(const float* __restrict__ cw)
{
    const int ho = blockIdx.x, hin = threadIdx.x;
    #pragma unroll
    for (int s = 0; s < 3; ++s) {
        float w = cw[(size_t)ho * (HH * 3) + hin * 3 + s];
        __half a = __float2half(w);
        __half r = __float2half((w - __half2float(a)) * WRES_UP);
        size_t o = (size_t)ho * (3 * HH) + s * HH + hin;
        g_b1[o] = a; g_b2[o] = r;
    }
    int idx = blockIdx.x * 1024 + hin;
    if (idx < BB * TCNT) g_partial[idx] = 0.f;
}

// =====================================================================
// K1: conv-as-GEMM via mma.sync fp16 split. grid (12, 8, 16), 256 thr.
// D[t,ho] = sum_{s,hin} X[t+s-1,hin] W[ho,hin,s]
//         = A1*B1 + (A1*2^-10)*(B2*2^10) + A2*B1   (single f32 accum)
// Epilogue reduces silu(D+cb)*pw over ho into g_partial[b,t].
// =====================================================================
__global__ void __launch_bounds__(256, 1)
k1_gemm(const float* __restrict__ cb, const float* __restrict__ pw)
{
    extern __shared__ char sm[];
    const uint32_t smb = smem_u32(sm);
    const int tid = threadIdx.x, lane = tid & 31, w = tid >> 5;
    const int wm = w & 3, wn = w >> 2;                  // 4 m-warps x 2 n-warps
    const int b = blockIdx.z, ho0 = blockIdx.y * 128, t0 = blockIdx.x * 128;

    float* s_cb = (float*)(sm + OFF_CB);
    float* s_pw = (float*)(sm + OFF_PW);
    if (tid < 128) {
        s_cb[tid] = cb[ho0 + tid];
        s_pw[tid] = pw[ho0 + tid];
    }

    float acc[2][8][4];
    #pragma unroll
    for (int ms = 0; ms < 2; ++ms)
        #pragma unroll
        for (int ns = 0; ns < 8; ++ns)
            #pragma unroll
            for (int c = 0; c < 4; ++c) acc[ms][ns][c] = 0.f;

    // ---- chunk loader: chunk i = (s = i%3, hc = i/3), 64 hin cols ----
    auto load_chunk = [&](int i, int st) {
        const int s = i % 3, hc = i / 3;
        const uint32_t SA = smb + st * STG;
        #pragma unroll
        for (int k = 0; k < 4; ++k) {
            const int lin = tid + (k << 8);
            const int row = lin >> 3, c = lin & 7;
            uint32_t off = (row << 7) + (((c ^ (row & 7)) & 7) << 4);
            // A: rows t0+s-1+row, cols hc*64 + c*8
            int t = t0 + s - 1 + row;
            bool v = ((unsigned)t < (unsigned)TCNT);
            size_t ga = ((size_t)b * TCNT + (v ? t : 0)) * HH + hc * 64 + c * 8;
            uint32_t nb = v ? 16u : 0u;
            cpa16(SA + OFF_A1 + off, g_a1 + ga, nb);
            cpa16(SA + OFF_A2 + off, g_a2 + ga, nb);
            // B: rows ho0+row, cols s*1024 + hc*64 + c*8
            size_t gb = (size_t)(ho0 + row) * (3 * HH) + s * HH + hc * 64 + c * 8;
            cpa16(SA + OFF_B1 + off, g_b1 + gb, 16u);
            cpa16(SA + OFF_B2 + off, g_b2 + gb, 16u);
        }
        cpa_commit();
    };

    load_chunk(0, 0);

    for (int i = 0; i < NCH; ++i) {
        const int st = i & 1;
        if (i + 1 < NCH) { load_chunk(i + 1, (i + 1) & 1); cpa_wait1(); }
        else             { cpa_wait0(); }
        __syncthreads();

        const uint32_t SA = smb + st * STG;
        #pragma unroll
        for (int ks = 0; ks < 4; ++ks) {
            uint32_t a1f[2][4], a2f[2][4], a1s[2][4];
            #pragma unroll
            for (int ms = 0; ms < 2; ++ms) {
                int arow = wm * 32 + ms * 16 + (lane & 15);
                int ac16 = ks * 2 + (lane >> 4);
                uint32_t aoff = (arow << 7) + (((ac16 ^ (arow & 7)) & 7) << 4);
                ldsm4(a1f[ms], SA + OFF_A1 + aoff);
                ldsm4(a2f[ms], SA + OFF_A2 + aoff);
                #pragma unroll
                for (int j = 0; j < 4; ++j)
                    a1s[ms][j] = hmul2(a1f[ms][j], HSC_DOWN);   // exact * 2^-10
            }
            #pragma unroll
            for (int ng = 0; ng < 4; ++ng) {
                int brow = wn * 64 + ng * 16 + (lane & 15);
                int bc16 = ks * 2 + (lane >> 4);
                uint32_t boff = (brow << 7) + (((bc16 ^ (brow & 7)) & 7) << 4);
                uint32_t b1f[4], b2f[4];
                ldsm4(b1f, SA + OFF_B1 + boff);   // non-trans: B stored [N,K]
                ldsm4(b2f, SA + OFF_B2 + boff);
                #pragma unroll
                for (int ms = 0; ms < 2; ++ms) {
                    mma16816(acc[ms][2 * ng],     a1f[ms], b1f[0], b1f[2]);
                    mma16816(acc[ms][2 * ng + 1], a1f[ms], b1f[1], b1f[3]);
                    mma16816(acc[ms][2 * ng],     a1s[ms], b2f[0], b2f[2]);
                    mma16816(acc[ms][2 * ng + 1], a1s[ms], b2f[1], b2f[3]);
                    mma16816(acc[ms][2 * ng],     a2f[ms], b1f[0], b1f[2]);
                    mma16816(acc[ms][2 * ng + 1], a2f[ms], b1f[1], b1f[3]);
                }
            }
        }
        __syncthreads();
    }

    // ---- epilogue: silu(acc+cb)*pw reduced over this CTA's 128 ho ----
    #pragma unroll
    for (int ms = 0; ms < 2; ++ms) {
        float r0 = 0.f, r1 = 0.f;   // rows (lane>>2) and (lane>>2)+8
        #pragma unroll
        for (int ns = 0; ns < 8; ++ns) {
            int col = wn * 64 + ns * 8 + (lane & 3) * 2;
            float f0 = acc[ms][ns][0] + s_cb[col];
            float f1 = acc[ms][ns][1] + s_cb[col + 1];
            float f2 = acc[ms][ns][2] + s_cb[col];
            float f3 = acc[ms][ns][3] + s_cb[col + 1];
            r0 += __fdividef(f0, 1.f + __expf(-f0)) * s_pw[col];
            r0 += __fdividef(f1, 1.f + __expf(-f1)) * s_pw[col + 1];
            r1 += __fdividef(f2, 1.f + __expf(-f2)) * s_pw[col];
            r1 += __fdividef(f3, 1.f + __expf(-f3)) * s_pw[col + 1];
        }
        r0 += __shfl_xor_sync(0xffffffffu, r0, 1);
        r0 += __shfl_xor_sync(0xffffffffu, r0, 2);
        r1 += __shfl_xor_sync(0xffffffffu, r1, 1);
        r1 += __shfl_xor_sync(0xffffffffu, r1, 2);
        if ((lane & 3) == 0) {
            int tb = t0 + wm * 32 + ms * 16 + (lane >> 2);
            if (tb < TCNT)     atomicAdd(&g_partial[b * TCNT + tb], r0);
            if (tb + 8 < TCNT) atomicAdd(&g_partial[b * TCNT + tb + 8], r1);
        }
    }
}

// =====================================================================
// K2: raw = softplus(partial + pb) + 1e-4 masked; mass, scale, cumsum.
// =====================================================================
__global__ void k2_scan(const int* __restrict__ ttl, const int* __restrict__ elen,
                        const float* __restrict__ pb)
{
    const int b = blockIdx.x;
    const int tid = threadIdx.x;   // 512
    __shared__ float smr[16];
    __shared__ float wsum[16];
    __shared__ float sh_scale, sh_carry;

    if (tid < MAXTOK) g_colsum[b * MAXTOK + tid] = 0.f;
    const float pbv = pb[0];
    const int el = elen[b];

    float local = 0.f;
    for (int t = tid; t < TCNT; t += 512) {
        float x = g_partial[b * TCNT + t] + pbv;
        float sp = (x > 20.f) ? x : log1pf(__expf(x));
        float r = sp + 1e-4f;
        if (t >= el) r = 0.f;
        g_raw[b * TCNT + t] = r;
        local += r;
    }
    #pragma unroll
    for (int off = 16; off > 0; off >>= 1)
        local += __shfl_xor_sync(0xffffffffu, local, off);
    if ((tid & 31) == 0) smr[tid >> 5] = local;
    __syncthreads();
    if (tid < 16) {
        float v = smr[tid];
        #pragma unroll
        for (int off = 8; off > 0; off >>= 1)
            v += __shfl_xor_sync(0x0000ffffu, v, off);
        if (tid == 0) {
            int tok = clip_tok(ttl[b]);
            g_massdiff[b] = fabsf(v - (float)tok);
            sh_scale = (float)tok / fmaxf(v, 1e-6f);
            sh_carry = 0.f;
        }
    }
    __syncthreads();
    const float scale = sh_scale;

    for (int tile = 0; tile < 3; ++tile) {
        int t = tile * 512 + tid;
        float v = (t < TCNT) ? g_raw[b * TCNT + t] * scale : 0.f;
        float x = v;
        #pragma unroll
        for (int off = 1; off < 32; off <<= 1) {
            float y = __shfl_up_sync(0xffffffffu, x, off);
            if ((tid & 31) >= off) x += y;
        }
        if ((tid & 31) == 31) wsum[tid >> 5] = x;
        __syncthreads();
        if (tid < 16) {
            float y = wsum[tid];
            #pragma unroll
            for (int off = 1; off < 16; off <<= 1) {
                float z = __shfl_up_sync(0x0000ffffu, y, off);
                if (tid >= off) y += z;
            }
            wsum[tid] = y;
        }
        __syncthreads();
        float offset = (tid >= 32) ? wsum[(tid >> 5) - 1] : 0.f;
        float incl = sh_carry + offset + x;
        if (t < TCNT) {
            g_cen[b * TCNT + t] = incl - 0.5f * v;
            g_sw[b * TCNT + t]  = v;
        }
        __syncthreads();
        if (tid == 0) sh_carry += wsum[15];
        __syncthreads();
    }
}

// =====================================================================
// K3: assign + colsums
// =====================================================================
__global__ void k3_assign()
{
    const int b  = blockIdx.y;
    const int t0 = blockIdx.x * TS;
    const int k  = threadIdx.x;   // 192
    __shared__ float sc[TS], ss[TS];
    if (k < TS) {
        sc[k] = g_cen[b * TCNT + t0 + k];
        ss[k] = g_sw[b * TCNT + t0 + k];
    }
    __syncthreads();
    const float tc = (float)k + 0.5f;
    float acc = 0.f;
    float* ap = g_assign + ((size_t)b * TCNT + t0) * MAXTOK + k;
    #pragma unroll 6
    for (int i = 0; i < TS; ++i) {
        float d = sc[i] - tc;
        float a = __expf(-d * d * INV2T2) * ss[i];
        ap[(size_t)i * MAXTOK] = a;
        acc += a;
    }
    atomicAdd(&g_colsum[b * MAXTOK + k], acc);
}

__global__ void k3b_rnorm(const int* __restrict__ ttl)
{
    int b = blockIdx.x, k = threadIdx.x;
    int tok = clip_tok(ttl[b]);
    float cs = g_colsum[b * MAXTOK + k];
    g_rnorm[b * MAXTOK + k] = (k < tok) ? 1.0f / fmaxf(cs, 1e-6f) : 0.f;
}

// =====================================================================
// K4: acoustic[b,k,h] = sum_t assign*rnorm * enc
// =====================================================================
__global__ void __launch_bounds__(256)
k4_gemm(const float* __restrict__ enc, float* __restrict__ out)
{
    const int b  = blockIdx.z;
    const int k0 = blockIdx.y * 64;
    const int h0 = blockIdx.x * 64;
    __shared__ float es[16][65];
    __shared__ float as[16][64];
    __shared__ float rn[64];
    const int tid = threadIdx.x;
    const int tx = tid & 15, ty = tid >> 4;
    if (tid < 64) rn[tid] = g_rnorm[b * MAXTOK + k0 + tid];

    float c[4][4];
    #pragma unroll
    for (int j = 0; j < 4; ++j)
        #pragma unroll
        for (int i = 0; i < 4; ++i) c[j][i] = 0.f;

    const float* encb = enc + ((size_t)b * HH + h0) * TCNT;
    const float* ab   = g_assign + (size_t)b * TCNT * MAXTOK + k0;

    for (int t0 = 0; t0 < TCNT; t0 += 16) {
        #pragma unroll
        for (int l = tid; l < 1024; l += 256) {
            int hh = l >> 4, tt = l & 15; int t = t0 + tt;
            es[tt][hh] = (t < TCNT) ? encb[(size_t)hh * TCNT + t] : 0.f;
        }
        #pragma unroll
        for (int l = tid; l < 1024; l += 256) {
            int tt = l >> 6, kk = l & 63; int t = t0 + tt;
            as[tt][kk] = (t < TCNT) ? ab[(size_t)t * MAXTOK + kk] : 0.f;
        }
        __syncthreads();
        #pragma unroll
        for (int tt = 0; tt < 16; ++tt) {
            float av[4], bv[4];
            #pragma unroll
            for (int i = 0; i < 4; ++i) av[i] = es[tt][ty * 4 + i];
            #pragma unroll
            for (int j = 0; j < 4; ++j) bv[j] = as[tt][tx * 4 + j];
            #pragma unroll
            for (int j = 0; j < 4; ++j)
                #pragma unroll
                for (int i = 0; i < 4; ++i) c[j][i] += bv[j] * av[i];
        }
        __syncthreads();
    }
    #pragma unroll
    for (int j = 0; j < 4; ++j) {
        float rj = rn[tx * 4 + j];
        float4 v = make_float4(c[j][0] * rj, c[j][1] * rj, c[j][2] * rj, c[j][3] * rj);
        *(float4*)(out + (((size_t)b * MAXTOK) + (k0 + tx * 4 + j)) * HH + h0 + ty * 4) = v;
    }
}

// =====================================================================
// K5: tail outputs
// =====================================================================
__global__ void k5_final(float* __restrict__ out, const int* __restrict__ ttl, int out_size)
{
    __shared__ float s_loss;
    int tid = threadIdx.x;
    float v = (tid < BB) ? g_massdiff[tid] : 0.f;
    #pragma unroll
    for (int off = 16; off > 0; off >>= 1)
        v += __shfl_xor_sync(0xffffffffu, v, off);
    if (tid == 0) s_loss = v * (0.25f / (float)BB);
    __syncthreads();
    const int base = BB * MAXTOK * HH;
    for (int i = base + tid; i < out_size; i += blockDim.x) {
        int r = i - base;
        float val = 0.f;
        if (r < BB)       val = (float)clip_tok(ttl[r]);
        else if (r == BB) val = s_loss;
        out[i] = val;
    }
}

// =====================================================================
extern "C" void kernel_launch(void* const* d_in, const int* in_sizes, int n_in,
                              void* d_out, int out_size)
{
    const float* enc  = (const float*)d_in[0];
    const int*   elen = (const int*)  d_in[1];
    const int*   ttl  = (const int*)  d_in[2];
    const float* cw   = (const float*)d_in[3];
    const float* cb   = (const float*)d_in[4];
    const float* pw   = (const float*)d_in[5];
    const float* pb   = (const float*)d_in[6];
    float* out = (float*)d_out;

    cudaFuncSetAttribute(k1_gemm, cudaFuncAttributeMaxDynamicSharedMemorySize, SMEM_K1);

    p_enc<<<dim3(47, 32, BB), dim3(32, 8)>>>(enc);
    p_w<<<HH, HH>>>(cw);
    k1_gemm<<<dim3(12, 8, BB), 256, SMEM_K1>>>(cb, pw);
    k2_scan<<<BB, 512>>>(ttl, elen, pb);
    k3_assign<<<dim3(NTILE, BB), MAXTOK>>>();
    k3b_rnorm<<<BB, MAXTOK>>>(ttl);
    k4_gemm<<<dim3(16, 3, BB), 256>>>(enc, out);
    if (out_size > BB * MAXTOK * HH)
        k5_final<<<1, 64>>>(out, ttl, out_size);
}

// round 17
// speedup vs baseline: 2.9491x; 1.1457x over previous
#include <cuda_runtime.h>
#include <cuda_fp16.h>
#include <cstdint>
#include <math.h>

#define BB     16
#define HH     1024
#define TCNT   1500
#define MAXTOK 192
#define TS     30
#define NTILE  50
#define INV2T2 4.0816326530612246f

// ---- K1 HMMA GEMM config (BM=128 t, BN=256 ho, 512 threads) ----
#define NCH    48            // 3 shifts * 16 hin-chunks of 64
#define OFF_A1 0
#define OFF_A2 16384
#define OFF_B1 32768
#define OFF_B2 65536
#define STG    98304         // bytes per pipeline stage
#define OFF_CB 196608        // 256 floats
#define OFF_PW 197632        // 256 floats
#define SMEM_K1 198656

// ---- K4 HMMA config (BM=64 k, BN=128 h, BK=32 t, 256 threads) ----
#define K4_SMA   5120        // A split per stage: 64 rows * 80B
#define K4_OFF_B1 0          // [2 stages][8192]
#define K4_OFF_B2 16384
#define K4_OFF_A1 32768      // [2 stages][5120]
#define K4_OFF_A2 43008
#define K4_OFF_RN 53248      // 64 floats
#define K4_SMEM   53504
#define K4_NS     47         // ceil(1500/32)

// ---------------- scratch (__device__ globals; no allocation) ----------------
static __device__ float  g_raw[BB * TCNT];
static __device__ float  g_sw[BB * TCNT];
static __device__ float  g_cen[BB * TCNT];
static __device__ float  g_assign[BB * TCNT * MAXTOK];
static __device__ float  g_colsum[BB * MAXTOK];
static __device__ float  g_rnorm[BB * MAXTOK];
static __device__ float  g_massdiff[BB];
static __device__ float  g_partial[BB * TCNT];
static __device__ __align__(128) __half g_a1[(size_t)BB * TCNT * HH];  // x1 [b,t,h]
static __device__ __align__(128) __half g_a2[(size_t)BB * TCNT * HH];  // x-x1
static __device__ __align__(128) __half g_b1[(size_t)HH * 3 * HH];     // w1 [ho, s*1024+hin]
static __device__ __align__(128) __half g_b2[(size_t)HH * 3 * HH];     // w-w1

__device__ __forceinline__ int clip_tok(int t) {
    return t < 1 ? 1 : (t > MAXTOK ? MAXTOK : t);
}

// ---------------- PTX helpers (base-target safe) ----------------
__device__ __forceinline__ uint32_t smem_u32(const void* p) {
    uint32_t a;
    asm("{ .reg .u64 t; cvta.to.shared.u64 t, %1; cvt.u32.u64 %0, t; }" : "=r"(a) : "l"(p));
    return a;
}
__device__ __forceinline__ void cpa16(uint32_t dst, const void* src, uint32_t nbytes) {
    asm volatile("cp.async.cg.shared.global [%0], [%1], 16, %2;"
                 :: "r"(dst), "l"(src), "r"(nbytes) : "memory");
}
__device__ __forceinline__ void cpa_commit() {
    asm volatile("cp.async.commit_group;" ::: "memory");
}
__device__ __forceinline__ void cpa_wait1() {
    asm volatile("cp.async.wait_group 1;" ::: "memory");
}
__device__ __forceinline__ void cpa_wait0() {
    asm volatile("cp.async.wait_group 0;" ::: "memory");
}
__device__ __forceinline__ void ldsm4(uint32_t* r, uint32_t a) {
    asm volatile("ldmatrix.sync.aligned.m8n8.x4.shared.b16 {%0,%1,%2,%3}, [%4];"
                 : "=r"(r[0]), "=r"(r[1]), "=r"(r[2]), "=r"(r[3]) : "r"(a));
}
__device__ __forceinline__ void ldsm4t(uint32_t* r, uint32_t a) {
    asm volatile("ldmatrix.sync.aligned.m8n8.x4.trans.shared.b16 {%0,%1,%2,%3}, [%4];"
                 : "=r"(r[0]), "=r"(r[1]), "=r"(r[2]), "=r"(r[3]) : "r"(a));
}
__device__ __forceinline__ void mma16816(float* c, const uint32_t* a, uint32_t b0, uint32_t b1) {
    asm volatile(
        "mma.sync.aligned.m16n8k16.row.col.f32.f16.f16.f32 "
        "{%0,%1,%2,%3}, {%4,%5,%6,%7}, {%8,%9}, {%0,%1,%2,%3};"
        : "+f"(c[0]), "+f"(c[1]), "+f"(c[2]), "+f"(c[3])
        : "r"(a[0]), "r"(a[1]), "r"(a[2]), "r"(a[3]), "r"(b0), "r"(b1));
}

// =====================================================================
// P1: transpose + fp16-split enc [b,h,t] -> g_a1/g_a2 [b,t,h]
// grid (47, 32, 16), block (32, 8)
// =====================================================================
__global__ void p_enc(const float* __restrict__ enc)
{
    __shared__ float tile[32][33];
    const int b = blockIdx.z, h0 = blockIdx.y * 32, t0 = blockIdx.x * 32;
    const int tx = threadIdx.x, ty = threadIdx.y;
    #pragma unroll
    for (int j = 0; j < 4; ++j) {
        int h = h0 + ty + 8 * j, t = t0 + tx;
        tile[ty + 8 * j][tx] = (t < TCNT) ? enc[((size_t)b * HH + h) * TCNT + t] : 0.f;
    }
    __syncthreads();
    #pragma unroll
    for (int j = 0; j < 4; ++j) {
        int t = t0 + ty + 8 * j, h = h0 + tx;
        if (t < TCNT) {
            float v = tile[tx][ty + 8 * j];
            __half a = __float2half(v);
            __half r = __float2half(v - __half2float(a));
            size_t o = ((size_t)b * TCNT + t) * HH + h;
            g_a1[o] = a; g_a2[o] = r;
        }
    }
}

// P2: expand + split weights; zero g_partial. grid(1024), block(1024)
__global__ void p_w(const float* __restrict__ cw)
{
    const int ho = blockIdx.x, hin = threadIdx.x;
    #pragma unroll
    for (int s = 0; s < 3; ++s) {
        float w = cw[(size_t)ho * (HH * 3) + hin * 3 + s];
        __half a = __float2half(w);
        __half r = __float2half(w - __half2float(a));
        size_t o = (size_t)ho * (3 * HH) + s * HH + hin;
        g_b1[o] = a; g_b2[o] = r;
    }
    int idx = blockIdx.x * 1024 + hin;
    if (idx < BB * TCNT) g_partial[idx] = 0.f;
}

// =====================================================================
// K1: conv-as-GEMM via mma.sync fp16 split. grid (12, 4, 16), 512 thr.
// D[t,ho] = A1*B1 + A1*B2 + A2*B1 (single f32 accum), then
// epilogue reduces silu(D+cb)*pw over ho into g_partial[b,t].
// =====================================================================
__global__ void __launch_bounds__(512, 1)
k1_gemm(const float* __restrict__ cb, const float* __restrict__ pw)
{
    extern __shared__ char sm[];
    const uint32_t smb = smem_u32(sm);
    const int tid = threadIdx.x, lane = tid & 31, w = tid >> 5;
    const int wm = w & 3, wn = w >> 2;                  // 4 m-warps x 4 n-warps
    const int b = blockIdx.z, ho0 = blockIdx.y * 256, t0 = blockIdx.x * 128;

    float* s_cb = (float*)(sm + OFF_CB);
    float* s_pw = (float*)(sm + OFF_PW);
    if (tid < 256) {
        s_cb[tid] = cb[ho0 + tid];
        s_pw[tid] = pw[ho0 + tid];
    }

    float acc[2][8][4];
    #pragma unroll
    for (int ms = 0; ms < 2; ++ms)
        #pragma unroll
        for (int ns = 0; ns < 8; ++ns)
            #pragma unroll
            for (int c = 0; c < 4; ++c) acc[ms][ns][c] = 0.f;

    // ---- chunk loader: chunk i = (s = i%3, hc = i/3), 64 hin cols ----
    auto load_chunk = [&](int i, int st) {
        const int s = i % 3, hc = i / 3;
        const uint32_t SA = smb + st * STG;
        // A: 128 rows x 8 c16 per split = 1024 chunks; 512 thr -> 2 each
        #pragma unroll
        for (int k = 0; k < 2; ++k) {
            const int lin = tid + (k << 9);
            const int row = lin >> 3, c = lin & 7;
            uint32_t off = (row << 7) + (((c ^ (row & 7)) & 7) << 4);
            int t = t0 + s - 1 + row;
            bool v = ((unsigned)t < (unsigned)TCNT);
            size_t ga = ((size_t)b * TCNT + (v ? t : 0)) * HH + hc * 64 + c * 8;
            uint32_t nb = v ? 16u : 0u;
            cpa16(SA + OFF_A1 + off, g_a1 + ga, nb);
            cpa16(SA + OFF_A2 + off, g_a2 + ga, nb);
        }
        // B: 256 rows x 8 c16 per split = 2048 chunks; 512 thr -> 4 each
        #pragma unroll
        for (int k = 0; k < 4; ++k) {
            const int lin = tid + (k << 9);
            const int row = lin >> 3, c = lin & 7;
            uint32_t off = (row << 7) + (((c ^ (row & 7)) & 7) << 4);
            size_t gb = (size_t)(ho0 + row) * (3 * HH) + s * HH + hc * 64 + c * 8;
            cpa16(SA + OFF_B1 + off, g_b1 + gb, 16u);
            cpa16(SA + OFF_B2 + off, g_b2 + gb, 16u);
        }
        cpa_commit();
    };

    load_chunk(0, 0);

    for (int i = 0; i < NCH; ++i) {
        const int st = i & 1;
        if (i + 1 < NCH) { load_chunk(i + 1, (i + 1) & 1); cpa_wait1(); }
        else             { cpa_wait0(); }
        __syncthreads();

        const uint32_t SA = smb + st * STG;
        #pragma unroll
        for (int ks = 0; ks < 4; ++ks) {
            uint32_t a1f[2][4], a2f[2][4];
            #pragma unroll
            for (int ms = 0; ms < 2; ++ms) {
                int arow = wm * 32 + ms * 16 + (lane & 15);
                int ac16 = ks * 2 + (lane >> 4);
                uint32_t aoff = (arow << 7) + (((ac16 ^ (arow & 7)) & 7) << 4);
                ldsm4(a1f[ms], SA + OFF_A1 + aoff);
                ldsm4(a2f[ms], SA + OFF_A2 + aoff);
            }
            #pragma unroll
            for (int ng = 0; ng < 4; ++ng) {
                int brow = wn * 64 + ng * 16 + (lane & 15);
                int bc16 = ks * 2 + (lane >> 4);
                uint32_t boff = (brow << 7) + (((bc16 ^ (brow & 7)) & 7) << 4);
                uint32_t b1f[4], b2f[4];
                ldsm4(b1f, SA + OFF_B1 + boff);   // B stored [N,K] -> non-trans
                ldsm4(b2f, SA + OFF_B2 + boff);
                #pragma unroll
                for (int ms = 0; ms < 2; ++ms) {
                    mma16816(acc[ms][2 * ng],     a1f[ms], b1f[0], b1f[2]);
                    mma16816(acc[ms][2 * ng + 1], a1f[ms], b1f[1], b1f[3]);
                    mma16816(acc[ms][2 * ng],     a1f[ms], b2f[0], b2f[2]);
                    mma16816(acc[ms][2 * ng + 1], a1f[ms], b2f[1], b2f[3]);
                    mma16816(acc[ms][2 * ng],     a2f[ms], b1f[0], b1f[2]);
                    mma16816(acc[ms][2 * ng + 1], a2f[ms], b1f[1], b1f[3]);
                }
            }
        }
        __syncthreads();
    }

    // ---- epilogue: silu(acc+cb)*pw reduced over this CTA's 256 ho ----
    #pragma unroll
    for (int ms = 0; ms < 2; ++ms) {
        float r0 = 0.f, r1 = 0.f;   // rows (lane>>2) and (lane>>2)+8
        #pragma unroll
        for (int ns = 0; ns < 8; ++ns) {
            int col = wn * 64 + ns * 8 + (lane & 3) * 2;
            float f0 = acc[ms][ns][0] + s_cb[col];
            float f1 = acc[ms][ns][1] + s_cb[col + 1];
            float f2 = acc[ms][ns][2] + s_cb[col];
            float f3 = acc[ms][ns][3] + s_cb[col + 1];
            r0 += __fdividef(f0, 1.f + __expf(-f0)) * s_pw[col];
            r0 += __fdividef(f1, 1.f + __expf(-f1)) * s_pw[col + 1];
            r1 += __fdividef(f2, 1.f + __expf(-f2)) * s_pw[col];
            r1 += __fdividef(f3, 1.f + __expf(-f3)) * s_pw[col + 1];
        }
        r0 += __shfl_xor_sync(0xffffffffu, r0, 1);
        r0 += __shfl_xor_sync(0xffffffffu, r0, 2);
        r1 += __shfl_xor_sync(0xffffffffu, r1, 1);
        r1 += __shfl_xor_sync(0xffffffffu, r1, 2);
        if ((lane & 3) == 0) {
            int tb = t0 + wm * 32 + ms * 16 + (lane >> 2);
            if (tb < TCNT)     atomicAdd(&g_partial[b * TCNT + tb], r0);
            if (tb + 8 < TCNT) atomicAdd(&g_partial[b * TCNT + tb + 8], r1);
        }
    }
}

// =====================================================================
// K2: raw = softplus(partial + pb) + 1e-4 masked; mass, scale, cumsum.
// =====================================================================
__global__ void k2_scan(const int* __restrict__ ttl, const int* __restrict__ elen,
                        const float* __restrict__ pb)
{
    const int b = blockIdx.x;
    const int tid = threadIdx.x;   // 512
    __shared__ float smr[16];
    __shared__ float wsum[16];
    __shared__ float sh_scale, sh_carry;

    if (tid < MAXTOK) g_colsum[b * MAXTOK + tid] = 0.f;
    const float pbv = pb[0];
    const int el = elen[b];

    float local = 0.f;
    for (int t = tid; t < TCNT; t += 512) {
        float x = g_partial[b * TCNT + t] + pbv;
        float sp = (x > 20.f) ? x : log1pf(__expf(x));
        float r = sp + 1e-4f;
        if (t >= el) r = 0.f;
        g_raw[b * TCNT + t] = r;
        local += r;
    }
    #pragma unroll
    for (int off = 16; off > 0; off >>= 1)
        local += __shfl_xor_sync(0xffffffffu, local, off);
    if ((tid & 31) == 0) smr[tid >> 5] = local;
    __syncthreads();
    if (tid < 16) {
        float v = smr[tid];
        #pragma unroll
        for (int off = 8; off > 0; off >>= 1)
            v += __shfl_xor_sync(0x0000ffffu, v, off);
        if (tid == 0) {
            int tok = clip_tok(ttl[b]);
            g_massdiff[b] = fabsf(v - (float)tok);
            sh_scale = (float)tok / fmaxf(v, 1e-6f);
            sh_carry = 0.f;
        }
    }
    __syncthreads();
    const float scale = sh_scale;

    for (int tile = 0; tile < 3; ++tile) {
        int t = tile * 512 + tid;
        float v = (t < TCNT) ? g_raw[b * TCNT + t] * scale : 0.f;
        float x = v;
        #pragma unroll
        for (int off = 1; off < 32; off <<= 1) {
            float y = __shfl_up_sync(0xffffffffu, x, off);
            if ((tid & 31) >= off) x += y;
        }
        if ((tid & 31) == 31) wsum[tid >> 5] = x;
        __syncthreads();
        if (tid < 16) {
            float y = wsum[tid];
            #pragma unroll
            for (int off = 1; off < 16; off <<= 1) {
                float z = __shfl_up_sync(0x0000ffffu, y, off);
                if (tid >= off) y += z;
            }
            wsum[tid] = y;
        }
        __syncthreads();
        float offset = (tid >= 32) ? wsum[(tid >> 5) - 1] : 0.f;
        float incl = sh_carry + offset + x;
        if (t < TCNT) {
            g_cen[b * TCNT + t] = incl - 0.5f * v;
            g_sw[b * TCNT + t]  = v;
        }
        __syncthreads();
        if (tid == 0) sh_carry += wsum[15];
        __syncthreads();
    }
}

// =====================================================================
// K3: assign + colsums
// =====================================================================
__global__ void k3_assign()
{
    const int b  = blockIdx.y;
    const int t0 = blockIdx.x * TS;
    const int k  = threadIdx.x;   // 192
    __shared__ float sc[TS], ss[TS];
    if (k < TS) {
        sc[k] = g_cen[b * TCNT + t0 + k];
        ss[k] = g_sw[b * TCNT + t0 + k];
    }
    __syncthreads();
    const float tc = (float)k + 0.5f;
    float acc = 0.f;
    float* ap = g_assign + ((size_t)b * TCNT + t0) * MAXTOK + k;
    #pragma unroll 6
    for (int i = 0; i < TS; ++i) {
        float d = sc[i] - tc;
        float a = __expf(-d * d * INV2T2) * ss[i];
        ap[(size_t)i * MAXTOK] = a;
        acc += a;
    }
    atomicAdd(&g_colsum[b * MAXTOK + k], acc);
}

__global__ void k3b_rnorm(const int* __restrict__ ttl)
{
    int b = blockIdx.x, k = threadIdx.x;
    int tok = clip_tok(ttl[b]);
    float cs = g_colsum[b * MAXTOK + k];
    g_rnorm[b * MAXTOK + k] = (k < tok) ? 1.0f / fmaxf(cs, 1e-6f) : 0.f;
}

// =====================================================================
// K4: acoustic[b,k,h] = sum_t assign[b,t,k]*rnorm[b,k]*enc[b,t,h]
// HMMA fp16-split: A = assign (split on the fly), B = enc (g_a1/g_a2,
// [t,h] layout -> ldmatrix.trans). BM=64 k, BN=128 h, BK=32 t.
// grid (8, 3, 16), 256 thr (2m x 4n warps).
// =====================================================================
__global__ void __launch_bounds__(256, 1)
k4_hmma(float* __restrict__ out)
{
    extern __shared__ char sm4[];
    const uint32_t smb = smem_u32(sm4);
    const int tid = threadIdx.x, lane = tid & 31, w = tid >> 5;
    const int wm = w & 1, wn = w >> 1;                  // 2m x 4n
    const int b = blockIdx.z, k0 = blockIdx.y * 64, h0 = blockIdx.x * 128;

    if (tid < 64)
        ((float*)(sm4 + K4_OFF_RN))[tid] = g_rnorm[b * MAXTOK + k0 + tid];

    float acc[2][4][4];
    #pragma unroll
    for (int ms = 0; ms < 2; ++ms)
        #pragma unroll
        for (int ns = 0; ns < 4; ++ns)
            #pragma unroll
            for (int c = 0; c < 4; ++c) acc[ms][ns][c] = 0.f;

    const float*  agm = g_assign + (size_t)b * TCNT * MAXTOK + k0;
    const __half* b1g = g_a1 + (size_t)b * TCNT * HH + h0;
    const __half* b2g = g_a2 + (size_t)b * TCNT * HH + h0;

    auto loadA = [&](int i, float* av) {
        #pragma unroll
        for (int e = 0; e < 8; ++e) {
            int idx = tid + (e << 8);
            int tt = idx >> 6, kk = idx & 63;
            int t = i * 32 + tt;
            av[e] = (t < TCNT) ? agm[(size_t)t * MAXTOK + kk] : 0.f;
        }
    };
    auto storeA = [&](int st, const float* av) {
        #pragma unroll
        for (int e = 0; e < 8; ++e) {
            int idx = tid + (e << 8);
            int tt = idx >> 6, kk = idx & 63;
            float v = av[e];
            __half a = __float2half(v);
            __half r = __float2half(v - __half2float(a));
            *(__half*)(sm4 + K4_OFF_A1 + st * K4_SMA + kk * 80 + tt * 2) = a;
            *(__half*)(sm4 + K4_OFF_A2 + st * K4_SMA + kk * 80 + tt * 2) = r;
        }
    };
    auto loadB = [&](int i, int st) {
        #pragma unroll
        for (int e = 0; e < 2; ++e) {
            int idx = tid + (e << 8);
            int row = idx >> 4, c16 = idx & 15;
            int t = i * 32 + row;
            bool v = (t < TCNT);
            const __half* s1 = b1g + (size_t)(v ? t : 0) * HH + c16 * 8;
            const __half* s2 = b2g + (size_t)(v ? t : 0) * HH + c16 * 8;
            uint32_t c16s = (c16 & 8) | ((c16 ^ (row & 7)) & 7);
            uint32_t off = row * 256 + c16s * 16;
            uint32_t nb = v ? 16u : 0u;
            cpa16(smb + K4_OFF_B1 + st * 8192 + off, s1, nb);
            cpa16(smb + K4_OFF_B2 + st * 8192 + off, s2, nb);
        }
        cpa_commit();
    };

    // prologue
    float av[8];
    loadA(0, av);
    loadB(0, 0);
    storeA(0, av);
    cpa_wait0();
    __syncthreads();

    for (int i = 0; i < K4_NS; ++i) {
        const int cur = i & 1, nxt = cur ^ 1;
        float av2[8];
        const bool more = (i + 1 < K4_NS);
        if (more) { loadA(i + 1, av2); loadB(i + 1, nxt); }

        const uint32_t BA1 = smb + K4_OFF_B1 + cur * 8192;
        const uint32_t BA2 = smb + K4_OFF_B2 + cur * 8192;
        const uint32_t AA1 = smb + K4_OFF_A1 + cur * K4_SMA;
        const uint32_t AA2 = smb + K4_OFF_A2 + cur * K4_SMA;

        #pragma unroll
        for (int ks = 0; ks < 2; ++ks) {
            uint32_t a1f[2][4], a2f[2][4];
            #pragma unroll
            for (int ms = 0; ms < 2; ++ms) {
                int arow = wm * 32 + ms * 16 + (lane & 15);
                int ac16 = ks * 2 + (lane >> 4);
                uint32_t aoff = arow * 80 + ac16 * 16;
                ldsm4(a1f[ms], AA1 + aoff);
                ldsm4(a2f[ms], AA2 + aoff);
            }
            #pragma unroll
            for (int ng = 0; ng < 2; ++ng) {
                int krow = ks * 16 + (lane & 7) + ((lane >> 4) << 3);
                int c16  = wn * 4 + ng * 2 + ((lane >> 3) & 1);
                uint32_t c16s = (c16 & 8) | ((c16 ^ (krow & 7)) & 7);
                uint32_t boff = krow * 256 + c16s * 16;
                uint32_t b1f[4], b2f[4];
                ldsm4t(b1f, BA1 + boff);   // [K,N] storage + trans
                ldsm4t(b2f, BA2 + boff);
                #pragma unroll
                for (int ms = 0; ms < 2; ++ms) {
                    int ns = ng * 2;
                    mma16816(acc[ms][ns],     a1f[ms], b1f[0], b1f[2]);
                    mma16816(acc[ms][ns + 1], a1f[ms], b1f[1], b1f[3]);
                    mma16816(acc[ms][ns],     a1f[ms], b2f[0], b2f[2]);
                    mma16816(acc[ms][ns + 1], a1f[ms], b2f[1], b2f[3]);
                    mma16816(acc[ms][ns],     a2f[ms], b1f[0], b1f[2]);
                    mma16816(acc[ms][ns + 1], a2f[ms], b1f[1], b1f[3]);
                }
            }
        }

        if (more) {
            storeA(nxt, av2);
            cpa_wait0();
            __syncthreads();
        }
    }

    // epilogue: scale by rnorm[k], store float2 pairs
    const float* rn = (const float*)(sm4 + K4_OFF_RN);
    float* outb = out + ((size_t)b * MAXTOK + k0) * HH + h0;
    #pragma unroll
    for (int ms = 0; ms < 2; ++ms) {
        int kr = wm * 32 + ms * 16 + (lane >> 2);
        float r0 = rn[kr], r1 = rn[kr + 8];
        #pragma unroll
        for (int ns = 0; ns < 4; ++ns) {
            int h = wn * 32 + ns * 8 + 2 * (lane & 3);
            float2 v0 = make_float2(acc[ms][ns][0] * r0, acc[ms][ns][1] * r0);
            float2 v1 = make_float2(acc[ms][ns][2] * r1, acc[ms][ns][3] * r1);
            *(float2*)(outb + (size_t)kr * HH + h) = v0;
            *(float2*)(outb + (size_t)(kr + 8) * HH + h) = v1;
        }
    }
}

// =====================================================================
// K5: tail outputs
// =====================================================================
__global__ void k5_final(float* __restrict__ out, const int* __restrict__ ttl, int out_size)
{
    __shared__ float s_loss;
    int tid = threadIdx.x;
    float v = (tid < BB) ? g_massdiff[tid] : 0.f;
    #pragma unroll
    for (int off = 16; off > 0; off >>= 1)
        v += __shfl_xor_sync(0xffffffffu, v, off);
    if (tid == 0) s_loss = v * (0.25f / (float)BB);
    __syncthreads();
    const int base = BB * MAXTOK * HH;
    for (int i = base + tid; i < out_size; i += blockDim.x) {
        int r = i - base;
        float val = 0.f;
        if (r < BB)       val = (float)clip_tok(ttl[r]);
        else if (r == BB) val = s_loss;
        out[i] = val;
    }
}

// =====================================================================
extern "C" void kernel_launch(void* const* d_in, const int* in_sizes, int n_in,
                              void* d_out, int out_size)
{
    const float* enc  = (const float*)d_in[0];
    const int*   elen = (const int*)  d_in[1];
    const int*   ttl  = (const int*)  d_in[2];
    const float* cw   = (const float*)d_in[3];
    const float* cb   = (const float*)d_in[4];
    const float* pw   = (const float*)d_in[5];
    const float* pb   = (const float*)d_in[6];
    float* out = (float*)d_out;

    cudaFuncSetAttribute(k1_gemm, cudaFuncAttributeMaxDynamicSharedMemorySize, SMEM_K1);
    cudaFuncSetAttribute(k4_hmma, cudaFuncAttributeMaxDynamicSharedMemorySize, K4_SMEM);

    p_enc<<<dim3(47, 32, BB), dim3(32, 8)>>>(enc);
    p_w<<<HH, HH>>>(cw);
    k1_gemm<<<dim3(12, 4, BB), 512, SMEM_K1>>>(cb, pw);
    k2_scan<<<BB, 512>>>(ttl, elen, pb);
    k3_assign<<<dim3(NTILE, BB), MAXTOK>>>();
    k3b_rnorm<<<BB, MAXTOK>>>(ttl);
    k4_hmma<<<dim3(8, 3, BB), 256, K4_SMEM>>>(out);
    if (out_size > BB * MAXTOK * HH)
        k5_final<<<1, 64>>>(out, ttl, out_size);
}